// round 6
// baseline (speedup 1.0000x reference)
#include <cuda_runtime.h>
#include <cstdint>
#include <math.h>
#include <cub/cub.cuh>

// ---------------------------------------------------------------------------
// MaskPath, jax_threefry_partitionable semantics (verified R3, rel_err=0).
// Counting sort by row + per-row insertion sort (R4) with the CORRECT mask
// semantics from R3: edge at global sorted position j is masked iff
// j < N && hit[j], where hit[] is indexed by *hit node id used as position*
// (the reference's e_id quirk).
// Output (float32, 5*E): remaining[2,E], masked[2,E], edge_mask[E] (1.0/0.0)
// ---------------------------------------------------------------------------

#define EMAX 16000000
#define NN 1000000
static const int TPB = 256;

__device__ int           g_deg[NN + 1];
__device__ int           g_rowptr[NN + 1];
__device__ int           g_cursor[NN];
__device__ int           g_colbuf[EMAX];
__device__ unsigned char g_temp[67108864];      // cub temp (64 MB)
__device__ unsigned int  g_pk_a[NN];
__device__ unsigned int  g_pk_b[NN];
__device__ unsigned int  g_pv_a[NN];
__device__ unsigned int  g_pv_b[NN];
__device__ int           g_hit[NN + 1];
__device__ int           g_hsum[NN + 1];

// ---------------- threefry2x32 (jax/_src/prng.py) ---------------------------
__host__ __device__ __forceinline__
void tf2x32(uint32_t k0, uint32_t k1, uint32_t x0, uint32_t x1,
            uint32_t& o0, uint32_t& o1) {
    uint32_t ks2 = k0 ^ k1 ^ 0x1BD11BDAu;
    x0 += k0; x1 += k1;
#define TF_R(r) { x0 += x1; x1 = (x1 << (r)) | (x1 >> (32 - (r))); x1 ^= x0; }
    TF_R(13) TF_R(15) TF_R(26) TF_R(6)   x0 += k1;  x1 += ks2 + 1u;
    TF_R(17) TF_R(29) TF_R(16) TF_R(24)  x0 += ks2; x1 += k0  + 2u;
    TF_R(13) TF_R(15) TF_R(26) TF_R(6)   x0 += k0;  x1 += k1  + 3u;
    TF_R(17) TF_R(29) TF_R(16) TF_R(24)  x0 += k1;  x1 += ks2 + 4u;
    TF_R(13) TF_R(15) TF_R(26) TF_R(6)   x0 += ks2; x1 += k0  + 5u;
#undef TF_R
    o0 = x0; o1 = x1;
}

__device__ __forceinline__
uint32_t jax_bits_part(uint2 k, uint32_t i) {
    uint32_t y0, y1;
    tf2x32(k.x, k.y, 0u, i, y0, y1);
    return y0 ^ y1;
}

static inline uint2 h_split(uint2 k, uint32_t i) {
    uint32_t y0, y1;
    tf2x32(k.x, k.y, 0u, i, y0, y1);
    return make_uint2(y0, y1);
}

// ------------------------------- kernels -----------------------------------
__global__ void k_zero(int* __restrict__ a, int n) {
    int i = blockIdx.x * blockDim.x + threadIdx.x;
    if (i < n) a[i] = 0;
}

__global__ void k_hist(const int* __restrict__ ei, int E, int* __restrict__ deg) {
    int i = blockIdx.x * blockDim.x + threadIdx.x;
    if (i >= E) return;
    atomicAdd(&deg[ei[i]], 1);
}

__global__ void k_copy(const int* __restrict__ src, int* __restrict__ dst, int n) {
    int i = blockIdx.x * blockDim.x + threadIdx.x;
    if (i < n) dst[i] = src[i];
}

__global__ void k_scatter(const int* __restrict__ ei, int E,
                          int* __restrict__ cursor, int* __restrict__ colbuf) {
    int i = blockIdx.x * blockDim.x + threadIdx.x;
    if (i >= E) return;
    int r = ei[i];
    int c = ei[(size_t)E + i];
    int pos = atomicAdd(&cursor[r], 1);
    colbuf[pos] = c;
}

__global__ void k_rowsort(const int* __restrict__ rowptr,
                          int* __restrict__ colbuf, int N) {
    int r = blockIdx.x * blockDim.x + threadIdx.x;
    if (r >= N) return;
    int lo = rowptr[r], hi = rowptr[r + 1];
    for (int j = lo + 1; j < hi; j++) {
        int v = colbuf[j];
        int k = j - 1;
        while (k >= lo && colbuf[k] > v) { colbuf[k + 1] = colbuf[k]; k--; }
        colbuf[k + 1] = v;
    }
}

__global__ void k_permbits(unsigned int* __restrict__ out_keys,
                           unsigned int* __restrict__ vals_init,
                           int n, uint2 key) {
    int i = blockIdx.x * blockDim.x + threadIdx.x;
    if (i >= n) return;
    out_keys[i] = jax_bits_part(key, (uint32_t)i);
    if (vals_init) vals_init[i] = (unsigned)i;
}

__global__ void k_walk(const unsigned int* __restrict__ start,
                       const int* __restrict__ rowptr,
                       const int* __restrict__ colbuf,
                       int* __restrict__ hit,
                       uint2 kt0, uint2 kt1, uint2 kt2, int S) {
    int i = blockIdx.x * blockDim.x + threadIdx.x;
    if (i >= S) return;
    uint2 kt[3] = { kt0, kt1, kt2 };
    int cur = (int)start[i];
    bool active = true;
#pragma unroll
    for (int t = 0; t < 3; t++) {
        int rp = rowptr[cur];
        int d  = rowptr[cur + 1] - rp;
        bool act = active && (d > 0);
        if (act) {
            hit[cur] = 1;            // e_id = current node, used as EDGE index
            uint32_t b = jax_bits_part(kt[t], (uint32_t)i);
            float u = __uint_as_float((b >> 9) | 0x3f800000u) - 1.0f;
            int off = (int)floorf(u * (float)d);
            int dm1 = d - 1;
            off = off > dm1 ? dm1 : off;
            off = off < 0 ? 0 : off;
            cur = colbuf[rp + off];
        }
        active = act;
    }
}

// Emit per row: positions j in [rowptr[r], rowptr[r+1]).
// Edge at global sorted position j is masked iff j < N && hit[j].
__global__ void k_emit(const int* __restrict__ rowptr,
                       const int* __restrict__ colbuf,
                       const int* __restrict__ hit,
                       const int* __restrict__ hsum,
                       float* __restrict__ rem0, float* __restrict__ rem1,
                       float* __restrict__ msk0, float* __restrict__ msk1,
                       float* __restrict__ maskv, int N) {
    int r = blockIdx.x * blockDim.x + threadIdx.x;
    if (r >= N) return;
    int lo = rowptr[r], hi = rowptr[r + 1];
    float fr = (float)r;
    int M = hsum[N];
    for (int j = lo; j < hi; j++) {
        float fc = (float)colbuf[j];
        if (j < N && hit[j]) {
            int p = hsum[j];
            msk0[p] = fr; msk1[p] = fc;
            maskv[j] = 0.0f;
        } else {
            int p = j - (j < N ? hsum[j] : M);
            rem0[p] = fr; rem1[p] = fc;
            maskv[j] = 1.0f;
        }
    }
}

__global__ void k_fill_rem(const int* __restrict__ Mp,
                           float* __restrict__ rem0, float* __restrict__ rem1,
                           int E) {
    int idx = blockIdx.x * blockDim.x + threadIdx.x;
    int M = __ldg(Mp);
    if (idx >= M) return;
    int j = E - M + idx;
    rem0[j] = -1.0f; rem1[j] = -1.0f;
}

__global__ void k_fill_msk(const int* __restrict__ Mp,
                           float* __restrict__ msk0, float* __restrict__ msk1,
                           int E) {
    int i = blockIdx.x * blockDim.x + threadIdx.x;
    if (i >= E) return;
    int M = __ldg(Mp);
    if (i >= M) { msk0[i] = -1.0f; msk1[i] = -1.0f; }
}

// ------------------------------- launcher ----------------------------------
extern "C" void kernel_launch(void* const* d_in, const int* in_sizes, int n_in,
                              void* d_out, int out_size) {
    (void)n_in; (void)out_size;
    const int* ei = (const int*)d_in[0];
    const int E = in_sizes[0] / 2;
    const int N = NN;

    float* out = (float*)d_out;
    float* rem0 = out;
    float* rem1 = out + (size_t)E;
    float* msk0 = out + 2 * (size_t)E;
    float* msk1 = out + 3 * (size_t)E;
    float* maskv = out + 4 * (size_t)E;

    void *pdeg, *prp, *pcur, *pcol, *pt, *ppka, *ppkb, *ppva, *ppvb, *phit, *phs;
    cudaGetSymbolAddress(&pdeg, g_deg);
    cudaGetSymbolAddress(&prp, g_rowptr);
    cudaGetSymbolAddress(&pcur, g_cursor);
    cudaGetSymbolAddress(&pcol, g_colbuf);
    cudaGetSymbolAddress(&pt, g_temp);
    cudaGetSymbolAddress(&ppka, g_pk_a);
    cudaGetSymbolAddress(&ppkb, g_pk_b);
    cudaGetSymbolAddress(&ppva, g_pv_a);
    cudaGetSymbolAddress(&ppvb, g_pv_b);
    cudaGetSymbolAddress(&phit, g_hit);
    cudaGetSymbolAddress(&phs, g_hsum);
    int* deg = (int*)pdeg;
    int* rowptr = (int*)prp;
    int* cursor = (int*)pcur;
    int* colbuf = (int*)pcol;
    unsigned char* tmp = (unsigned char*)pt;
    unsigned int* pk_a = (unsigned int*)ppka;
    unsigned int* pk_b = (unsigned int*)ppkb;
    unsigned int* pv_a = (unsigned int*)ppva;
    unsigned int* pv_b = (unsigned int*)ppvb;
    int* hit = (int*)phit;
    int* hsum = (int*)phs;

    // ---- host-side jax key derivations (key(42)), partitionable semantics ----
    uint2 key42 = make_uint2(0u, 42u);
    uint2 kperm = h_split(key42, 0u);
    uint2 kwalk = h_split(key42, 1u);
    uint2 key1 = h_split(kperm, 0u);
    uint2 sub1 = h_split(kperm, 1u);
    uint2 sub2 = h_split(key1, 1u);
    uint2 kt0 = h_split(kwalk, 0u);
    uint2 kt1 = h_split(kwalk, 1u);
    uint2 kt2 = h_split(kwalk, 2u);

    const int S = (int)llround((double)N * 0.7);   // 700000

    cudaStream_t st = 0;
    const int gE = (E + TPB - 1) / TPB;
    const int gN = (N + TPB - 1) / TPB;
    const int gN1 = (N + 1 + TPB - 1) / TPB;

    // 1) counting sort by row + per-row col sort
    k_zero<<<gN1, TPB, 0, st>>>(deg, N + 1);
    k_hist<<<gE, TPB, 0, st>>>(ei, E, deg);
    size_t tb1 = 0;
    cub::DeviceScan::ExclusiveSum(nullptr, tb1, deg, rowptr, N + 1, st);
    cub::DeviceScan::ExclusiveSum(tmp, tb1, deg, rowptr, N + 1, st);
    k_copy<<<gN, TPB, 0, st>>>(rowptr, cursor, N);
    k_scatter<<<gE, TPB, 0, st>>>(ei, E, cursor, colbuf);
    k_rowsort<<<gN, TPB, 0, st>>>(rowptr, colbuf, N);

    // 2) jax permutation: 2 stable sort-by-bits rounds (1M pairs)
    k_permbits<<<gN, TPB, 0, st>>>(pk_a, pv_a, N, sub1);
    size_t tb2 = 0;
    cub::DeviceRadixSort::SortPairs(nullptr, tb2, pk_a, pk_b, pv_a, pv_b, N, 0, 32, st);
    cub::DeviceRadixSort::SortPairs(tmp, tb2, pk_a, pk_b, pv_a, pv_b, N, 0, 32, st);
    k_permbits<<<gN, TPB, 0, st>>>(pk_a, (unsigned int*)nullptr, N, sub2);
    size_t tb3 = 0;
    cub::DeviceRadixSort::SortPairs(nullptr, tb3, pk_a, pk_b, pv_b, pv_a, N, 0, 32, st);
    cub::DeviceRadixSort::SortPairs(tmp, tb3, pk_a, pk_b, pv_b, pv_a, N, 0, 32, st);

    // 3) random walks -> hit flags (node id used as edge-position index)
    k_zero<<<gN1, TPB, 0, st>>>(hit, N + 1);
    k_walk<<<(S + TPB - 1) / TPB, TPB, 0, st>>>(pv_a, rowptr, colbuf, hit,
                                                kt0, kt1, kt2, S);

    // 4) prefix sum of hits (hsum[N] = total masked M)
    size_t tb4 = 0;
    cub::DeviceScan::ExclusiveSum(nullptr, tb4, hit, hsum, N + 1, st);
    cub::DeviceScan::ExclusiveSum(tmp, tb4, hit, hsum, N + 1, st);

    // 5) compaction + mask output
    k_emit<<<gN, TPB, 0, st>>>(rowptr, colbuf, hit, hsum,
                               rem0, rem1, msk0, msk1, maskv, N);
    k_fill_rem<<<gE, TPB, 0, st>>>(hsum + N, rem0, rem1, E);
    k_fill_msk<<<gE, TPB, 0, st>>>(hsum + N, msk0, msk1, E);
}